// round 14
// baseline (speedup 1.0000x reference)
#include <cuda_runtime.h>
#include <cuda_bf16.h>
#include <cstdint>

// SpectralInverse, linearized tail + tensorized Y, M=64 per warp:
//   out[p,o] = u_b[o] + sum_f cos(2pi*Y[p,f]) * G[f,o],  G = h.u_w^T/N (precomputed bf16)
//   Y via m16n8k16 split-MMA; each 8-cos group feeds an m16n8k8 main MMA.
//   4 M-tiles per warp share every B-fragment load -> fixed cost amortized 4x.

#define BATCH 4
#define NF 128
#define CIN 64
#define COUT 8
#define NGRID (48*48*48)
#define TPB 256
#define PTS_PER_CTA 512
#define CTAS_PER_BATCH (NGRID / PTS_PER_CTA)   // 216
#define TWO_PI_F 6.28318530717958647692f
#define WBSTRIDE 136

__device__ uint32_t g_G[BATCH * 64 * COUT];    // bf16x2 words [batch][f/2][o]

__device__ __forceinline__ uint32_t pack_bf16x2(float lo, float hi) {
    uint32_t r;
    asm("cvt.rn.bf16x2.f32 %0, %1, %2;" : "=r"(r) : "f"(hi), "f"(lo));
    return r;
}
__device__ __forceinline__ float bf16rt(float x) {
    return __bfloat162float(__float2bfloat16(x));
}

// m16n8k16, D = A*B (fresh accumulator) — Y
__device__ __forceinline__ void mma16816_z(float* d,
                                            uint32_t a0, uint32_t a1, uint32_t a2, uint32_t a3,
                                            uint32_t b0, uint32_t b1) {
    asm volatile("mma.sync.aligned.m16n8k16.row.col.f32.bf16.bf16.f32 "
                 "{%0,%1,%2,%3}, {%4,%5,%6,%7}, {%8,%9}, {%10,%10,%10,%10};"
                 : "=f"(d[0]), "=f"(d[1]), "=f"(d[2]), "=f"(d[3])
                 : "r"(a0), "r"(a1), "r"(a2), "r"(a3), "r"(b0), "r"(b1), "f"(0.0f));
}
// m16n8k8, D += A*B — main contraction
__device__ __forceinline__ void mma1688_a(float* d, uint32_t a0, uint32_t a1, uint32_t b) {
    asm volatile("mma.sync.aligned.m16n8k8.row.col.f32.bf16.bf16.f32 "
                 "{%0,%1,%2,%3}, {%4,%5}, {%6}, {%0,%1,%2,%3};"
                 : "+f"(d[0]), "+f"(d[1]), "+f"(d[2]), "+f"(d[3])
                 : "r"(a0), "r"(a1), "r"(b));
}

// Position A-fragment word for k-slots (2t,2t+1) of [x_h,y_h,z_h,1, x_m,y_m,z_m,1]
__device__ __forceinline__ uint32_t apos(float4 q, int t) {
    float xh = bf16rt(q.x), yh = bf16rt(q.y), zh = bf16rt(q.z);
    if (t == 0) return pack_bf16x2(xh, yh);
    if (t == 1) return pack_bf16x2(zh, 1.0f);
    if (t == 2) return pack_bf16x2(q.x - xh, q.y - yh);
    return pack_bf16x2(q.z - zh, 1.0f);
}

// ---------------- kernel 1: G = h . u_w^T / N — one warp per G word ----------------
__global__ void __launch_bounds__(256)
precompute_G_kernel(const float* __restrict__ h, const float* __restrict__ u_w)
{
    const int w    = blockIdx.x * 8 + (threadIdx.x >> 5);
    const int lane = threadIdx.x & 31;
    const int b  = w >> 9;
    const int fp = (w >> 3) & 63;
    const int o  = w & 7;

    const float2* h0 = (const float2*)(h + ((size_t)b * NF + 2 * fp) * CIN);
    const float2* h1 = (const float2*)(h + ((size_t)b * NF + 2 * fp + 1) * CIN);
    const float2* uw = (const float2*)(u_w + o * CIN);

    float2 u  = uw[lane];
    float2 a0 = h0[lane];
    float2 a1 = h1[lane];
    float g0 = fmaf(a0.x, u.x, a0.y * u.y);
    float g1 = fmaf(a1.x, u.x, a1.y * u.y);
    #pragma unroll
    for (int off = 16; off > 0; off >>= 1) {
        g0 += __shfl_xor_sync(0xFFFFFFFFu, g0, off);
        g1 += __shfl_xor_sync(0xFFFFFFFFu, g1, off);
    }
    if (lane == 0) {
        const float inv_n = 1.0f / (float)NGRID;
        g_G[w] = pack_bf16x2(g0 * inv_n, g1 * inv_n);
    }
}

// ---------------- kernel 2: main ----------------
__global__ void __launch_bounds__(TPB, 4)
spectral_hmma11_kernel(const float* __restrict__ y,
                       const float* __restrict__ y_w,
                       const float* __restrict__ y_b,
                       const float* __restrict__ u_b,
                       float* __restrict__ out)
{
    __shared__ float4 s_pts[PTS_PER_CTA];      // 8192 B
    __shared__ uint2  s_wb[4 * WBSTRIDE];      // 4352 B (.x=pass1, .y=pass2)
    __shared__ uint2  s_G2[32 * COUT];         // 2048 B (.x=b(k0-7), .y=b(k8-15))
    __shared__ float  s_ub[COUT];

    const int tid  = threadIdx.x;
    const int warp = tid >> 5;
    const int lane = tid & 31;
    const int g = lane >> 2;
    const int t = lane & 3;
    const int bIdx = blockIdx.x / CTAS_PER_BATCH;
    const int blk  = blockIdx.x % CTAS_PER_BATCH;

    // ---- staging: Y-MMA B fragments ----
    {
        const int f = tid & 127;
        const int sec = tid >> 7;
        float wx = TWO_PI_F * y_w[f * 3], wy = TWO_PI_F * y_w[f * 3 + 1];
        float wz = TWO_PI_F * y_w[f * 3 + 2], bb = TWO_PI_F * y_b[f];
        float wxh = bf16rt(wx), wyh = bf16rt(wy), wzh = bf16rt(wz), bh_ = bf16rt(bb);
        float wxm = wx - wxh, wym = wy - wyh, wzm = wz - wzh, bm_ = bb - bh_;
        #pragma unroll
        for (int jj = 0; jj < 2; jj++) {
            int j = sec * 2 + jj;
            float lo1, hi1, lo2, hi2;
            if (j == 0 || j == 2) { lo1 = wxh; hi1 = wyh; lo2 = wxm; hi2 = wym; }
            else if (j == 1)      { lo1 = wzh; hi1 = bh_; lo2 = wzm; hi2 = 0.0f; }
            else                  { lo1 = wzh; hi1 = bm_; lo2 = wzm; hi2 = 0.0f; }
            s_wb[j * WBSTRIDE + f] = make_uint2(pack_bf16x2(lo1, hi1), pack_bf16x2(lo2, hi2));
        }
    }
    // ---- staging: grid positions (512 pts) ----
    {
        const float* yg = y + ((size_t)bIdx * NGRID + (size_t)blk * PTS_PER_CTA) * 3;
        float* sp = (float*)s_pts;
        #pragma unroll
        for (int it = 0; it < 8; it++) {
            int j = tid + it * TPB;
            int pt = j >> 2, c = j & 3;
            sp[j] = (c < 3) ? yg[pt * 3 + c] : 0.0f;
        }
    }
    // ---- staging: G words, relaid for per-kt LDS.64 ----
    #pragma unroll
    for (int it = 0; it < 2; it++) {
        int i = tid + it * TPB;
        int r = i >> 3, o = i & 7;
        uint32_t v = g_G[bIdx * (64 * COUT) + i];
        int kt = r >> 3, tt = r & 7;
        if (tt < 4) s_G2[(kt * 4 + tt) * 8 + o].x = v;
        else        s_G2[(kt * 4 + tt - 4) * 8 + o].y = v;
    }
    if (tid < COUT) s_ub[tid] = u_b[tid];
    __syncthreads();

    // ---- per-warp: M=64 rows x K=128 x N=8, 4 M-tiles ----
    const int base = warp * 64;

    uint32_t aP[8];
    #pragma unroll
    for (int tl = 0; tl < 4; tl++) {
        aP[2 * tl]     = apos(s_pts[base + tl * 16 + g],     t);
        aP[2 * tl + 1] = apos(s_pts[base + tl * 16 + g + 8], t);
    }

    const float ub0 = s_ub[2 * t], ub1 = s_ub[2 * t + 1];
    float acc[4][4];
    #pragma unroll
    for (int tl = 0; tl < 4; tl++) {
        acc[tl][0] = ub0; acc[tl][1] = ub1; acc[tl][2] = ub0; acc[tl][3] = ub1;
    }

    const uint2* wb0 = s_wb + t * WBSTRIDE + g;
    const uint2* sg0 = s_G2 + t * 8 + g;

    #pragma unroll
    for (int kt = 0; kt < 8; kt++) {
        const uint2 bG = sg0[kt * 32];
        #pragma unroll
        for (int nt2 = 0; nt2 < 2; nt2++) {
            const uint2 c = wb0[kt * 16 + nt2 * 8];
            const uint32_t b = nt2 ? bG.y : bG.x;
            #pragma unroll
            for (int tl = 0; tl < 4; tl++) {
                float d[4];
                mma16816_z(d, aP[2 * tl], aP[2 * tl + 1], aP[2 * tl], aP[2 * tl + 1], c.x, c.y);
                uint32_t a0 = pack_bf16x2(__cosf(d[0]), __cosf(d[1]));
                uint32_t a1 = pack_bf16x2(__cosf(d[2]), __cosf(d[3]));
                mma1688_a(acc[tl], a0, a1, b);
            }
        }
    }

    const size_t pt = (size_t)bIdx * NGRID + (size_t)blk * PTS_PER_CTA + base + g;
    #pragma unroll
    for (int tl = 0; tl < 4; tl++) {
        *(float2*)(out + (pt + tl * 16 + 0) * COUT + 2 * t) = make_float2(acc[tl][0], acc[tl][1]);
        *(float2*)(out + (pt + tl * 16 + 8) * COUT + 2 * t) = make_float2(acc[tl][2], acc[tl][3]);
    }
}

extern "C" void kernel_launch(void* const* d_in, const int* in_sizes, int n_in,
                              void* d_out, int out_size) {
    const float* h   = (const float*)d_in[0];
    const float* y   = (const float*)d_in[1];
    const float* y_w = (const float*)d_in[2];
    const float* y_b = (const float*)d_in[3];
    const float* u_w = (const float*)d_in[4];
    const float* u_b = (const float*)d_in[5];
    float* out = (float*)d_out;

    precompute_G_kernel<<<256, 256>>>(h, u_w);
    dim3 grid(BATCH * CTAS_PER_BATCH);   // 864 CTAs
    spectral_hmma11_kernel<<<grid, TPB>>>(y, y_w, y_b, u_b, out);
}

// round 15
// speedup vs baseline: 1.4444x; 1.4444x over previous
#include <cuda_runtime.h>
#include <cuda_bf16.h>
#include <cstdint>

// SpectralInverse, linearized tail + tensorized Y:
//   out[p,o] = u_b[o] + sum_f cos(2pi*Y[p,f]) * G[f,o],  G = h.u_w^T/N (precomputed bf16)
//   Y via one m16n8k16 split-MMA per 8-col group (A k-slots [xh yh zh 1 | xm ym zm 1]).
// TPB=512 (16 warps, 512 pts/CTA): per-CTA staging amortized 2x vs TPB=256.
// Main body: R10 ordering (two 8-cos groups -> two k16 main MMAs) + uint2 LDS.64 merges.

#define BATCH 4
#define NF 128
#define CIN 64
#define COUT 8
#define NGRID (48*48*48)
#define TPB 512
#define PTS_PER_CTA 512
#define CTAS_PER_BATCH (NGRID / PTS_PER_CTA)   // 216
#define TWO_PI_F 6.28318530717958647692f
#define WBSTRIDE 136

__device__ uint32_t g_G[BATCH * 64 * COUT];    // bf16x2 words [batch][f/2][o]

__device__ __forceinline__ uint32_t pack_bf16x2(float lo, float hi) {
    uint32_t r;
    asm("cvt.rn.bf16x2.f32 %0, %1, %2;" : "=r"(r) : "f"(hi), "f"(lo));
    return r;  // r[15:0]=bf16(lo), r[31:16]=bf16(hi)
}
__device__ __forceinline__ float bf16rt(float x) {
    return __bfloat162float(__float2bfloat16(x));
}

__device__ __forceinline__ void mma16816(float* d,
                                          uint32_t a0, uint32_t a1, uint32_t a2, uint32_t a3,
                                          uint32_t b0, uint32_t b1) {
    asm volatile("mma.sync.aligned.m16n8k16.row.col.f32.bf16.bf16.f32 "
                 "{%0,%1,%2,%3}, {%4,%5,%6,%7}, {%8,%9}, {%0,%1,%2,%3};"
                 : "+f"(d[0]), "+f"(d[1]), "+f"(d[2]), "+f"(d[3])
                 : "r"(a0), "r"(a1), "r"(a2), "r"(a3), "r"(b0), "r"(b1));
}
__device__ __forceinline__ void mma16816_z(float* d,
                                            uint32_t a0, uint32_t a1, uint32_t a2, uint32_t a3,
                                            uint32_t b0, uint32_t b1) {
    asm volatile("mma.sync.aligned.m16n8k16.row.col.f32.bf16.bf16.f32 "
                 "{%0,%1,%2,%3}, {%4,%5,%6,%7}, {%8,%9}, {%10,%10,%10,%10};"
                 : "=f"(d[0]), "=f"(d[1]), "=f"(d[2]), "=f"(d[3])
                 : "r"(a0), "r"(a1), "r"(a2), "r"(a3), "r"(b0), "r"(b1), "f"(0.0f));
}

// Position A-fragment word for k-slots (2t,2t+1) of [x_h,y_h,z_h,1, x_m,y_m,z_m,1]
__device__ __forceinline__ uint32_t apos(float4 q, int t) {
    float xh = bf16rt(q.x), yh = bf16rt(q.y), zh = bf16rt(q.z);
    if (t == 0) return pack_bf16x2(xh, yh);
    if (t == 1) return pack_bf16x2(zh, 1.0f);
    if (t == 2) return pack_bf16x2(q.x - xh, q.y - yh);
    return pack_bf16x2(q.z - zh, 1.0f);
}

// ---------------- kernel 1: G = h . u_w^T / N — one warp per G word ----------------
__global__ void __launch_bounds__(256)
precompute_G_kernel(const float* __restrict__ h, const float* __restrict__ u_w)
{
    const int w    = blockIdx.x * 8 + (threadIdx.x >> 5);
    const int lane = threadIdx.x & 31;
    const int b  = w >> 9;
    const int fp = (w >> 3) & 63;
    const int o  = w & 7;

    const float2* h0 = (const float2*)(h + ((size_t)b * NF + 2 * fp) * CIN);
    const float2* h1 = (const float2*)(h + ((size_t)b * NF + 2 * fp + 1) * CIN);
    const float2* uw = (const float2*)(u_w + o * CIN);

    float2 u  = uw[lane];
    float2 a0 = h0[lane];
    float2 a1 = h1[lane];
    float g0 = fmaf(a0.x, u.x, a0.y * u.y);
    float g1 = fmaf(a1.x, u.x, a1.y * u.y);
    #pragma unroll
    for (int off = 16; off > 0; off >>= 1) {
        g0 += __shfl_xor_sync(0xFFFFFFFFu, g0, off);
        g1 += __shfl_xor_sync(0xFFFFFFFFu, g1, off);
    }
    if (lane == 0) {
        const float inv_n = 1.0f / (float)NGRID;
        g_G[w] = pack_bf16x2(g0 * inv_n, g1 * inv_n);
    }
}

// ---------------- kernel 2: main ----------------
__global__ void __launch_bounds__(TPB, 2)
spectral_hmma12_kernel(const float* __restrict__ y,
                       const float* __restrict__ y_w,
                       const float* __restrict__ y_b,
                       const float* __restrict__ u_b,
                       float* __restrict__ out)
{
    __shared__ float4 s_pts[PTS_PER_CTA];      // 8192 B
    __shared__ uint2  s_wb[4 * WBSTRIDE];      // 4352 B (.x=pass1, .y=pass2)
    __shared__ uint2  s_G2[32 * COUT];         // 2048 B (.x=b(k0-7), .y=b(k8-15))
    __shared__ float  s_ub[COUT];

    const int tid  = threadIdx.x;
    const int warp = tid >> 5;
    const int lane = tid & 31;
    const int g = lane >> 2;
    const int t = lane & 3;
    const int bIdx = blockIdx.x / CTAS_PER_BATCH;
    const int blk  = blockIdx.x % CTAS_PER_BATCH;

    // ---- staging: Y-MMA B fragments (1 entry per thread) ----
    {
        const int f = tid & 127;
        const int j = tid >> 7;                  // 0..3
        float wx = TWO_PI_F * y_w[f * 3], wy = TWO_PI_F * y_w[f * 3 + 1];
        float wz = TWO_PI_F * y_w[f * 3 + 2], bb = TWO_PI_F * y_b[f];
        float wxh = bf16rt(wx), wyh = bf16rt(wy), wzh = bf16rt(wz), bh_ = bf16rt(bb);
        float lo1, hi1, lo2, hi2;
        if (j == 0 || j == 2) { lo1 = wxh; hi1 = wyh; lo2 = wx - wxh; hi2 = wy - wyh; }
        else if (j == 1)      { lo1 = wzh; hi1 = bh_;      lo2 = wz - wzh; hi2 = 0.0f; }
        else                  { lo1 = wzh; hi1 = bb - bh_; lo2 = wz - wzh; hi2 = 0.0f; }
        s_wb[j * WBSTRIDE + f] = make_uint2(pack_bf16x2(lo1, hi1), pack_bf16x2(lo2, hi2));
    }
    // ---- staging: grid positions (512 pts) ----
    {
        const float* yg = y + ((size_t)bIdx * NGRID + (size_t)blk * PTS_PER_CTA) * 3;
        float* sp = (float*)s_pts;
        #pragma unroll
        for (int it = 0; it < 4; it++) {
            int j = tid + it * TPB;
            int pt = j >> 2, c = j & 3;
            sp[j] = (c < 3) ? yg[pt * 3 + c] : 0.0f;
        }
    }
    // ---- staging: G words, relaid for per-kt LDS.64 (1 word per thread) ----
    {
        int i = tid;                              // word id 0..511
        int r = i >> 3, o = i & 7;
        uint32_t v = g_G[bIdx * (64 * COUT) + i];
        int kt = r >> 3, tt = r & 7;
        if (tt < 4) s_G2[(kt * 4 + tt) * 8 + o].x = v;
        else        s_G2[(kt * 4 + tt - 4) * 8 + o].y = v;
    }
    if (tid < COUT) s_ub[tid] = u_b[tid];
    __syncthreads();

    // ---- per-warp: M=32 rows x K=128 x N=8 ----
    const int base = warp * 32;

    const uint32_t aP00 = apos(s_pts[base + g],      t);
    const uint32_t aP01 = apos(s_pts[base + g + 8],  t);
    const uint32_t aP10 = apos(s_pts[base + g + 16], t);
    const uint32_t aP11 = apos(s_pts[base + g + 24], t);

    const float ub0 = s_ub[2 * t], ub1 = s_ub[2 * t + 1];
    float acc0[4] = {ub0, ub1, ub0, ub1};
    float acc1[4] = {ub0, ub1, ub0, ub1};

    const uint2* wb0 = s_wb + t * WBSTRIDE + g;
    const uint2* sg0 = s_G2 + t * 8 + g;

    #pragma unroll
    for (int kt = 0; kt < 8; kt++) {
        const uint2 bG = sg0[kt * 32];            // .x = b(k0-7), .y = b(k8-15)
        uint32_t a0, a1, a2, a3, a4, a5, a6, a7;
        #pragma unroll
        for (int nt2 = 0; nt2 < 2; nt2++) {
            const uint2 c = wb0[kt * 16 + nt2 * 8];   // .x=pass1, .y=pass2
            float d0[4], d1[4];
            mma16816_z(d0, aP00, aP01, aP00, aP01, c.x, c.y);
            mma16816_z(d1, aP10, aP11, aP10, aP11, c.x, c.y);
            uint32_t f0 = pack_bf16x2(__cosf(d0[0]), __cosf(d0[1]));
            uint32_t f1 = pack_bf16x2(__cosf(d0[2]), __cosf(d0[3]));
            uint32_t f2 = pack_bf16x2(__cosf(d1[0]), __cosf(d1[1]));
            uint32_t f3 = pack_bf16x2(__cosf(d1[2]), __cosf(d1[3]));
            if (nt2 == 0) { a0 = f0; a1 = f1; a4 = f2; a5 = f3; }
            else          { a2 = f0; a3 = f1; a6 = f2; a7 = f3; }
        }
        mma16816(acc0, a0, a1, a2, a3, bG.x, bG.y);
        mma16816(acc1, a4, a5, a6, a7, bG.x, bG.y);
    }

    const size_t pt = (size_t)bIdx * NGRID + (size_t)blk * PTS_PER_CTA + base + g;
    *(float2*)(out + (pt +  0) * COUT + 2 * t) = make_float2(acc0[0], acc0[1]);
    *(float2*)(out + (pt +  8) * COUT + 2 * t) = make_float2(acc0[2], acc0[3]);
    *(float2*)(out + (pt + 16) * COUT + 2 * t) = make_float2(acc1[0], acc1[1]);
    *(float2*)(out + (pt + 24) * COUT + 2 * t) = make_float2(acc1[2], acc1[3]);
}

extern "C" void kernel_launch(void* const* d_in, const int* in_sizes, int n_in,
                              void* d_out, int out_size) {
    const float* h   = (const float*)d_in[0];
    const float* y   = (const float*)d_in[1];
    const float* y_w = (const float*)d_in[2];
    const float* y_b = (const float*)d_in[3];
    const float* u_w = (const float*)d_in[4];
    const float* u_b = (const float*)d_in[5];
    float* out = (float*)d_out;

    precompute_G_kernel<<<256, 256>>>(h, u_w);
    dim3 grid(BATCH * CTAS_PER_BATCH);   // 864 CTAs
    spectral_hmma12_kernel<<<grid, TPB>>>(y, y_w, y_b, u_b, out);
}